// round 4
// baseline (speedup 1.0000x reference)
#include <cuda_runtime.h>
#include <math.h>

constexpr int Bc=4, Sc=512, Dc=512, Ic=1024, Cc=32, NCc=16;
constexpr long long SD=(long long)Sc*Dc;
constexpr long long ID=(long long)Ic*Dc;
constexpr long long CI=(long long)Cc*Ic;
constexpr long long CD=(long long)Cc*Dc;
constexpr long long SI=(long long)Sc*Ic;

// ---------------- persistent device scratch ----------------
__device__ float g_k[Bc*Sc*Dc];
__device__ float g_v[Bc*Sc*Dc];
__device__ float g_q[Bc*Sc*Dc];
__device__ float g_theta[Bc*Sc];
__device__ float g_alpha[Bc*Sc];
__device__ float g_eta[Bc*Sc];
__device__ float g_MW1[Bc*Ic*Dc];
__device__ float g_SW1[Bc*Ic*Dc];
__device__ float g_MW2[Bc*Dc*Ic];
__device__ float g_SW2[Bc*Dc*Ic];
__device__ float g_Mln[Bc*Dc];
__device__ float g_Sln[Bc*Dc];
__device__ float g_z[Bc*Cc*Ic];
__device__ float g_h[Bc*Cc*Ic];
__device__ float g_o[Bc*Cc*Dc];
__device__ float g_do[Bc*Cc*Dc];
__device__ float g_gln[Bc*Cc*Dc];
__device__ float g_p[Bc*Cc*Ic];
__device__ float g_nk[Bc*Cc], g_ndo[Bc*Cc], g_ngl[Bc*Cc], g_nh[Bc*Cc];
__device__ float g_npp[Bc*Cc*16];
__device__ float g_sE[Bc*Cc], g_sc2[Bc*Cc];
__device__ float g_Ab[Bc], g_Bpb[Bc], g_cSb[Bc];
__device__ float g_hbuf[Bc*Sc*Ic];
__device__ float g_obuf[Bc*Sc*Dc];
__device__ int g_barCount;   // zero-init, returns to 0 after each barrier
__device__ int g_barGen;     // monotonically increasing (wraps OK)

__device__ __forceinline__ float sigmoidf(float v){ return 1.f/(1.f+expf(-v)); }

// ---------------- grid-wide barrier (all nb blocks guaranteed resident) ----------------
__device__ __forceinline__ void gridSync(int nb){
    __syncthreads();
    if(threadIdx.x==0){
        int gen = *((volatile int*)&g_barGen);
        __threadfence();
        if(atomicAdd(&g_barCount, 1) == nb-1){
            g_barCount = 0;
            __threadfence();
            atomicExch(&g_barGen, gen+1);
        } else {
            while(*((volatile int*)&g_barGen) == gen){ __nanosleep(40); }
            __threadfence();
        }
    }
    __syncthreads();
}

// ---------------- 512-thread block reduce ----------------
__device__ __forceinline__ float blockReduce(float v, float* sred){
    int lane = threadIdx.x & 31, w = threadIdx.x >> 5;
    #pragma unroll
    for(int o=16;o>0;o>>=1) v += __shfl_down_sync(0xffffffffu, v, o);
    if(lane==0) sred[w] = v;
    __syncthreads();
    if(w==0){
        float r = (lane < 16) ? sred[lane] : 0.f;
        #pragma unroll
        for(int o=8;o>0;o>>=1) r += __shfl_down_sync(0xffffffffu, r, o);
        if(lane==0) sred[32] = r;
    }
    __syncthreads();
    float r = sred[32];
    __syncthreads();
    return r;
}

// ---------------- NT tile 128x64, 512 threads. C[128,64] = A[128,K] @ B[64,K]^T ----------------
// mode 0: store, 1: silu
__device__ void nt128(const float* __restrict__ A, const float* __restrict__ B,
                      float* __restrict__ C, int K, int ldc, int mode, float* SH){
    float* As = SH;            // [32 kk][132] holds m
    float* Bs = SH + 4224;     // [32 kk][68] holds n
    const int tid = threadIdx.x;
    const int ty = tid>>4, tx = tid&15;      // rows ty*4..+3, cols tx*4..+3
    float acc[4][4];
    #pragma unroll
    for(int i=0;i<4;i++){ acc[i][0]=0.f; acc[i][1]=0.f; acc[i][2]=0.f; acc[i][3]=0.f; }
    const int am = tid>>2, akb = (tid&3)*8;
    const int bn = tid>>3, bkb = (tid&7)*4;
    for(int k0=0;k0<K;k0+=32){
        const float* ap = A + (long long)am*K + k0 + akb;
        float4 v0 = *(const float4*)ap;
        float4 v1 = *(const float4*)(ap+4);
        As[(akb+0)*132+am]=v0.x; As[(akb+1)*132+am]=v0.y; As[(akb+2)*132+am]=v0.z; As[(akb+3)*132+am]=v0.w;
        As[(akb+4)*132+am]=v1.x; As[(akb+5)*132+am]=v1.y; As[(akb+6)*132+am]=v1.z; As[(akb+7)*132+am]=v1.w;
        const float* bp = B + (long long)bn*K + k0 + bkb;
        float4 w = *(const float4*)bp;
        Bs[(bkb+0)*68+bn]=w.x; Bs[(bkb+1)*68+bn]=w.y; Bs[(bkb+2)*68+bn]=w.z; Bs[(bkb+3)*68+bn]=w.w;
        __syncthreads();
        #pragma unroll
        for(int kk=0;kk<32;kk++){
            float4 a = *(float4*)&As[kk*132 + ty*4];
            float4 b = *(float4*)&Bs[kk*68 + tx*4];
            acc[0][0]+=a.x*b.x; acc[0][1]+=a.x*b.y; acc[0][2]+=a.x*b.z; acc[0][3]+=a.x*b.w;
            acc[1][0]+=a.y*b.x; acc[1][1]+=a.y*b.y; acc[1][2]+=a.y*b.z; acc[1][3]+=a.y*b.w;
            acc[2][0]+=a.z*b.x; acc[2][1]+=a.z*b.y; acc[2][2]+=a.z*b.z; acc[2][3]+=a.z*b.w;
            acc[3][0]+=a.w*b.x; acc[3][1]+=a.w*b.y; acc[3][2]+=a.w*b.z; acc[3][3]+=a.w*b.w;
        }
        __syncthreads();
    }
    #pragma unroll
    for(int i=0;i<4;i++){
        int r = ty*4+i;
        float4 o4;
        o4.x=acc[i][0]; o4.y=acc[i][1]; o4.z=acc[i][2]; o4.w=acc[i][3];
        if(mode==1){
            o4.x *= sigmoidf(o4.x); o4.y *= sigmoidf(o4.y);
            o4.z *= sigmoidf(o4.z); o4.w *= sigmoidf(o4.w);
        }
        *(float4*)&C[(long long)r*ldc + tx*4] = o4;
    }
}

// ---------------- NT tile 32x64, 512 threads. mode 0: store, 2: Z raw + silu C ----------------
__device__ void nt32(const float* __restrict__ A, const float* __restrict__ B,
                     float* __restrict__ C, float* __restrict__ Z,
                     int K, int ldc, int mode, float* SH){
    float* As = SH;            // [32 kk][36] holds m (32)
    float* Bs = SH + 1152;     // [32 kk][68] holds n (64)
    const int tid = threadIdx.x;
    const int ty = tid>>4, tx = tid&15;  // row ty, cols tx*4
    float acc[4] = {0.f,0.f,0.f,0.f};
    const int bn = tid>>3, bkb = (tid&7)*4;
    for(int k0=0;k0<K;k0+=32){
        if(tid<256){
            int m = tid>>3, kb = (tid&7)*4;
            float4 v = *(const float4*)(A + (long long)m*K + k0 + kb);
            As[(kb+0)*36+m]=v.x; As[(kb+1)*36+m]=v.y; As[(kb+2)*36+m]=v.z; As[(kb+3)*36+m]=v.w;
        }
        {
            float4 w = *(const float4*)(B + (long long)bn*K + k0 + bkb);
            Bs[(bkb+0)*68+bn]=w.x; Bs[(bkb+1)*68+bn]=w.y; Bs[(bkb+2)*68+bn]=w.z; Bs[(bkb+3)*68+bn]=w.w;
        }
        __syncthreads();
        #pragma unroll
        for(int kk=0;kk<32;kk++){
            float a = As[kk*36+ty];
            float4 b = *(float4*)&Bs[kk*68+tx*4];
            acc[0]+=a*b.x; acc[1]+=a*b.y; acc[2]+=a*b.z; acc[3]+=a*b.w;
        }
        __syncthreads();
    }
    long long base = (long long)ty*ldc + tx*4;
    if(mode==2){
        float4 z4; z4.x=acc[0]; z4.y=acc[1]; z4.z=acc[2]; z4.w=acc[3];
        *(float4*)&Z[base] = z4;
        float4 h4;
        h4.x=acc[0]*sigmoidf(acc[0]); h4.y=acc[1]*sigmoidf(acc[1]);
        h4.z=acc[2]*sigmoidf(acc[2]); h4.w=acc[3]*sigmoidf(acc[3]);
        *(float4*)&C[base] = h4;
    } else {
        float4 o4; o4.x=acc[0]; o4.y=acc[1]; o4.z=acc[2]; o4.w=acc[3];
        *(float4*)&C[base] = o4;
    }
}

// ---------------- NN tile 32x64: P = (A@B) * dsilu(Z); also write |p|^2 row partials ----------------
__device__ void nn32_p(const float* __restrict__ A, const float* __restrict__ B,
                       const float* __restrict__ Z, float* __restrict__ P,
                       int K, int N, int ld, int b, int jtile, float* SH){
    float* As = SH;            // [32 kk][36]
    float* Bs = SH + 1152;     // [32 kk][68]
    const int tid = threadIdx.x;
    const int ty = tid>>4, tx = tid&15;
    float acc[4] = {0.f,0.f,0.f,0.f};
    const int bkk = tid>>4, bnb = (tid&15)*4;
    for(int k0=0;k0<K;k0+=32){
        if(tid<256){
            int m = tid>>3, kb = (tid&7)*4;
            float4 v = *(const float4*)(A + (long long)m*K + k0 + kb);
            As[(kb+0)*36+m]=v.x; As[(kb+1)*36+m]=v.y; As[(kb+2)*36+m]=v.z; As[(kb+3)*36+m]=v.w;
        }
        {
            float4 w = *(const float4*)(B + (long long)(k0+bkk)*N + bnb);
            *(float4*)&Bs[bkk*68+bnb] = w;
        }
        __syncthreads();
        #pragma unroll
        for(int kk=0;kk<32;kk++){
            float a = As[kk*36+ty];
            float4 b4 = *(float4*)&Bs[kk*68+tx*4];
            acc[0]+=a*b4.x; acc[1]+=a*b4.y; acc[2]+=a*b4.z; acc[3]+=a*b4.w;
        }
        __syncthreads();
    }
    long long base = (long long)ty*ld + tx*4;
    float4 z4 = *(const float4*)&Z[base];
    float p0,p1,p2,p3;
    { float s=sigmoidf(z4.x); p0=acc[0]*(s*(1.f+z4.x*(1.f-s))); }
    { float s=sigmoidf(z4.y); p1=acc[1]*(s*(1.f+z4.y*(1.f-s))); }
    { float s=sigmoidf(z4.z); p2=acc[2]*(s*(1.f+z4.z*(1.f-s))); }
    { float s=sigmoidf(z4.w); p3=acc[3]*(s*(1.f+z4.w*(1.f-s))); }
    float4 o4; o4.x=p0; o4.y=p1; o4.z=p2; o4.w=p3;
    *(float4*)&P[base] = o4;
    // row partial of |p|^2 over this 64-col tile: reduce across the 16 lanes of the row
    float part = p0*p0 + p1*p1 + p2*p2 + p3*p3;
    #pragma unroll
    for(int o=8;o>0;o>>=1) part += __shfl_xor_sync(0xffffffffu, part, o);
    if(tx==0) g_npp[(b*Cc+ty)*16 + jtile] = part;
}

// ---------------- clip coefs into shared (scf[0..31]=ce, scf[32..63]=cc) ----------------
__device__ void loadCoefs(int b, float* scf){
    const int tid = threadIdx.x;
    if(tid < 32){
        int t = tid;
        float np = 0.f;
        #pragma unroll
        for(int j=0;j<16;j++) np += g_npp[(b*Cc+t)*16 + j];
        float sq = np*g_nk[b*Cc+t] + g_ndo[b*Cc+t]*g_nh[b*Cc+t] + g_ngl[b*Cc+t];
        float coef = fminf(1.f/(sqrtf(sq)+1e-6f), 1.f);
        scf[t]    = g_sE[b*Cc+t]*coef;
        scf[32+t] = g_sc2[b*Cc+t]*coef;
    }
    __syncthreads();
}

// ---------------- rank-32 tile 64x64: S' = A*S - sum ce*p*k ; M' = Bp*M + cS*S - sum cc*p*k ----------------
__device__ void rankTile(float* __restrict__ Sm, float* __restrict__ Mm, int ldS,
                         const float* __restrict__ P, long long pStride,
                         const float* __restrict__ Kv, long long kStride,
                         const float* scf, float Acf, float Bp, float cS, float* SH){
    float* Ps = SH;            // [32 t][68]
    float* Ks = SH + 2176;
    const int tid = threadIdx.x;
    {
        int t = tid>>4, cb = (tid&15)*4;
        *(float4*)&Ps[t*68+cb] = *(const float4*)(P + (long long)t*pStride + cb);
        *(float4*)&Ks[t*68+cb] = *(const float4*)(Kv + (long long)t*kStride + cb);
    }
    __syncthreads();
    const int ty = tid>>4, tx = tid&15;   // rows ty*2..+1, cols tx*4..+3
    float ae[2][4]={{0.f,0.f,0.f,0.f},{0.f,0.f,0.f,0.f}};
    float ac[2][4]={{0.f,0.f,0.f,0.f},{0.f,0.f,0.f,0.f}};
    #pragma unroll
    for(int t=0;t<32;t++){
        float ce = scf[t], cc = scf[32+t];
        float p0 = Ps[t*68 + ty*2], p1 = Ps[t*68 + ty*2 + 1];
        float4 k4 = *(float4*)&Ks[t*68 + tx*4];
        float e0=ce*p0, e1=ce*p1, c0=cc*p0, c1=cc*p1;
        ae[0][0]+=e0*k4.x; ae[0][1]+=e0*k4.y; ae[0][2]+=e0*k4.z; ae[0][3]+=e0*k4.w;
        ae[1][0]+=e1*k4.x; ae[1][1]+=e1*k4.y; ae[1][2]+=e1*k4.z; ae[1][3]+=e1*k4.w;
        ac[0][0]+=c0*k4.x; ac[0][1]+=c0*k4.y; ac[0][2]+=c0*k4.z; ac[0][3]+=c0*k4.w;
        ac[1][0]+=c1*k4.x; ac[1][1]+=c1*k4.y; ac[1][2]+=c1*k4.z; ac[1][3]+=c1*k4.w;
    }
    #pragma unroll
    for(int i=0;i<2;i++){
        long long base = (long long)(ty*2+i)*ldS + tx*4;
        float4 s4 = *(float4*)&Sm[base];
        float4 m4 = *(float4*)&Mm[base];
        float4 ns, nm;
        ns.x = Acf*s4.x - ae[i][0]; nm.x = Bp*m4.x + cS*s4.x - ac[i][0];
        ns.y = Acf*s4.y - ae[i][1]; nm.y = Bp*m4.y + cS*s4.y - ac[i][1];
        ns.z = Acf*s4.z - ae[i][2]; nm.z = Bp*m4.z + cS*s4.z - ac[i][2];
        ns.w = Acf*s4.w - ae[i][3]; nm.w = Bp*m4.w + cS*s4.w - ac[i][3];
        *(float4*)&Sm[base] = ns;
        *(float4*)&Mm[base] = nm;
    }
    __syncthreads();
}

// ==================== THE MEGA KERNEL ====================
__global__ __launch_bounds__(512, 1) void mega_kernel(
    const float* __restrict__ x,  const float* __restrict__ wq, const float* __restrict__ wk,
    const float* __restrict__ wv, const float* __restrict__ qn, const float* __restrict__ kn,
    const float* __restrict__ alw,const float* __restrict__ thw,const float* __restrict__ etw,
    const float* __restrict__ w1, const float* __restrict__ w2, const float* __restrict__ lnw,
    float* __restrict__ out, int nb)
{
    __shared__ float SH[6400];
    __shared__ float sred[33];
    __shared__ float scf[96];
    const int bid = blockIdx.x, tid = threadIdx.x;

    // ---------- Phase 0: state init + gates ----------
    {
        const float4* w1_4 = (const float4*)w1;
        const float4* w2_4 = (const float4*)w2;
        float4 zero4; zero4.x=0.f; zero4.y=0.f; zero4.z=0.f; zero4.w=0.f;
        for(long long i4 = (long long)bid*512 + tid; i4 < ID/4; i4 += (long long)nb*512){
            float4 a = w1_4[i4], b2 = w2_4[i4];
            #pragma unroll
            for(int b=0;b<Bc;b++){
                ((float4*)g_MW1)[b*(ID/4) + i4] = a;
                ((float4*)g_SW1)[b*(ID/4) + i4] = zero4;
                ((float4*)g_MW2)[b*(ID/4) + i4] = b2;
                ((float4*)g_SW2)[b*(ID/4) + i4] = zero4;
            }
        }
        for(int i = bid*512 + tid; i < Dc; i += nb*512){
            float l = lnw[i];
            #pragma unroll
            for(int b=0;b<Bc;b++){ g_Mln[b*Dc+i] = l; g_Sln[b*Dc+i] = 0.f; }
        }
        // gates: warp per token
        int wid = tid>>5, lane = tid&31;
        for(int task = bid; task < 128; task += nb){
            int tok = task*16 + wid;
            const float* xr = x + (long long)tok*Dc;
            float st=0.f, sa=0.f, se=0.f;
            for(int j=lane; j<Dc; j+=32){
                float xv = xr[j];
                st += xv*thw[j]; sa += xv*alw[j]; se += xv*etw[j];
            }
            #pragma unroll
            for(int o=16;o>0;o>>=1){
                st += __shfl_down_sync(0xffffffffu, st, o);
                sa += __shfl_down_sync(0xffffffffu, sa, o);
                se += __shfl_down_sync(0xffffffffu, se, o);
            }
            if(lane==0){
                g_theta[tok] = 0.01f*sigmoidf(st);
                g_alpha[tok] = sigmoidf(sa);
                g_eta[tok]   = sigmoidf(se);
            }
        }
    }
    gridSync(nb);

    // ---------- Phase 1: projections k, v, q ----------
    for(int task = bid; task < 384; task += nb){
        int w = task >> 7, tile = task & 127;
        int mt = tile >> 3, nt = tile & 7;
        const float* W = (w==0) ? wk : ((w==1) ? wv : wq);
        float* dst = (w==0) ? g_k : ((w==1) ? g_v : g_q);
        nt128(x + (long long)mt*128*Dc, W + (long long)nt*64*Dc,
              dst + (long long)mt*128*Dc + nt*64, Dc, Dc, 0, SH);
    }
    gridSync(nb);

    // ---------- Phase 2: activations (silu / silu+rms) ----------
    for(int task = bid; task < 3*Bc*Sc; task += nb){
        int which = task / (Bc*Sc), row = task % (Bc*Sc);
        float* buf = (which==0) ? g_k : ((which==1) ? g_v : g_q);
        long long idx = (long long)row*Dc + tid;
        float v = buf[idx];
        float sv = v*sigmoidf(v);
        if(which==1){ buf[idx] = sv; }
        else{
            const float* wnorm = (which==0) ? kn : qn;
            float s2 = blockReduce(sv*sv, sred);
            float n = rsqrtf(s2*(1.f/Dc) + 1e-6f);
            buf[idx] = sv*n*wnorm[tid];
        }
    }
    gridSync(nb);

    // ---------- chunk loop ----------
    for(int ci=0; ci<NCc; ci++){
        // PA: z/h = (silu)(Kc @ W1^T)   tasks: 4b x 16 ntiles
        for(int task = bid; task < 64; task += nb){
            int b = task >> 4, nt = task & 15;
            nt32(g_k + ((long long)b*Sc + ci*Cc)*Dc,
                 g_MW1 + (long long)b*ID + (long long)nt*64*Dc,
                 g_h + (long long)b*CI + nt*64,
                 g_z + (long long)b*CI + nt*64,
                 Dc, Ic, 2, SH);
        }
        gridSync(nb);

        // PB: o = H @ W2^T   tasks: 4b x 8
        for(int task = bid; task < 32; task += nb){
            int b = task >> 3, nt = task & 7;
            nt32(g_h + (long long)b*CI,
                 g_MW2 + (long long)b*ID + (long long)nt*64*Ic,
                 g_o + (long long)b*CD + nt*64, nullptr,
                 Ic, Dc, 0, SH);
        }
        gridSync(nb);

        // PC: per-token backward through rms head; norms; scan-coef recurrence
        for(int task = bid; task < Bc*Cc; task += nb){
            int b = task >> 5, t = task & 31;
            int tok = ci*Cc + t;
            int d = tid;
            float kv = g_k[((long long)b*Sc + tok)*Dc + d];
            float vv = g_v[((long long)b*Sc + tok)*Dc + d];
            float ov = g_o[((long long)b*Cc + t)*Dc + d];
            float ln = g_Mln[b*Dc + d];
            float th = g_theta[b*Sc + tok];
            float s2 = blockReduce(ov*ov, sred);
            float n = rsqrtf(s2*(1.f/Dc) + 1e-6f);
            float y = ln*n*ov;
            float r = kv + y - vv;
            float u = (2.f/Dc)*th*r;
            float gl = u*n*ov;
            float ws = blockReduce(u*ov*ln, sred);
            float dov = n*ln*u - (n*n*n*ov*(1.f/Dc))*ws;
            g_do[((long long)b*Cc + t)*Dc + d] = dov;
            g_gln[((long long)b*Cc + t)*Dc + d] = gl;
            float hv0 = g_h[((long long)b*Cc + t)*Ic + d];
            float hv1 = g_h[((long long)b*Cc + t)*Ic + d + 512];
            float nk = blockReduce(kv*kv, sred);
            float nd = blockReduce(dov*dov, sred);
            float ng = blockReduce(gl*gl, sred);
            float nh = blockReduce(hv0*hv0 + hv1*hv1, sred);
            if(d==0){
                g_nk[b*Cc+t]=nk; g_ndo[b*Cc+t]=nd; g_ngl[b*Cc+t]=ng; g_nh[b*Cc+t]=nh;
            }
            if(t==0){
                // serial suffix recurrence for this batch
                if(tid < 32){
                    scf[tid]    = g_eta[b*Sc + ci*Cc + tid];
                    scf[32+tid] = 1.f - g_alpha[b*Sc + ci*Cc + tid];
                }
                __syncthreads();
                if(tid==0){
                    float E=1.f, F=1.f, c=1.f, cSv=0.f;
                    for(int s=Cc-1;s>=0;s--){
                        g_sE[b*Cc+s] = E;
                        g_sc2[b*Cc+s] = c;
                        if(s==0) cSv = scf[0]*c;
                        float Fn = scf[32+s]*F;
                        c = Fn + scf[s]*c;
                        E = scf[s]*E;
                        F = Fn;
                    }
                    g_Ab[b]=E; g_Bpb[b]=F; g_cSb[b]=cSv;
                }
                __syncthreads();
            }
        }
        gridSync(nb);

        // PD: p = (DO @ W2) * dsilu(z)  + |p|^2 partials   tasks: 4b x 16
        for(int task = bid; task < 64; task += nb){
            int b = task >> 4, nt = task & 15;
            nn32_p(g_do + (long long)b*CD,
                   g_MW2 + (long long)b*ID + nt*64,
                   g_z + (long long)b*CI + nt*64,
                   g_p + (long long)b*CI + nt*64,
                   Dc, Ic, Ic, b, nt, SH);
        }
        gridSync(nb);

        // PF: ln update (tasks 0..3) + rank updates W1 (4..515) + W2 (516..1027)
        for(int task = bid; task < 1028; task += nb){
            if(task < 4){
                int b = task;
                loadCoefs(b, scf);
                float Acf=g_Ab[b], Bp=g_Bpb[b], cS=g_cSb[b];
                int d = tid;
                float S = g_Sln[b*Dc+d], M = g_Mln[b*Dc+d];
                float se_=0.f, sc_=0.f;
                #pragma unroll
                for(int t=0;t<Cc;t++){
                    float g = g_gln[((long long)b*Cc + t)*Dc + d];
                    se_ += scf[t]*g;
                    sc_ += scf[32+t]*g;
                }
                g_Sln[b*Dc+d] = Acf*S - se_;
                g_Mln[b*Dc+d] = Bp*M + cS*S - sc_;
                __syncthreads();
            } else if(task < 516){
                int u = task - 4;
                int b = u >> 7, tile = u & 127;
                int rt = tile >> 3, ct = tile & 7;
                loadCoefs(b, scf);
                rankTile(g_SW1 + (long long)b*ID + (long long)rt*64*Dc + ct*64,
                         g_MW1 + (long long)b*ID + (long long)rt*64*Dc + ct*64, Dc,
                         g_p + (long long)b*CI + rt*64, Ic,
                         g_k + ((long long)b*Sc + ci*Cc)*Dc + ct*64, Dc,
                         scf, g_Ab[b], g_Bpb[b], g_cSb[b], SH);
            } else {
                int u = task - 516;
                int b = u >> 7, tile = u & 127;
                int rt = tile >> 4, ct = tile & 15;
                loadCoefs(b, scf);
                rankTile(g_SW2 + (long long)b*ID + (long long)rt*64*Ic + ct*64,
                         g_MW2 + (long long)b*ID + (long long)rt*64*Ic + ct*64, Ic,
                         g_do + (long long)b*CD + rt*64, Dc,
                         g_h + (long long)b*CI + ct*64, Ic,
                         scf, g_Ab[b], g_Bpb[b], g_cSb[b], SH);
            }
        }
        gridSync(nb);
    }

    // ---------- Phase 4: retrieval h = silu(q @ W1^T) ----------
    for(int task = bid; task < 256; task += nb){
        int b = task >> 6, tl = task & 63;
        int mt = tl >> 4, nt = tl & 15;
        nt128(g_q + (long long)b*SD + (long long)mt*128*Dc,
              g_MW1 + (long long)b*ID + (long long)nt*64*Dc,
              g_hbuf + (long long)b*SI + (long long)mt*128*Ic + nt*64,
              Dc, Ic, 1, SH);
    }
    gridSync(nb);

    // ---------- Phase 5: obuf = hbuf @ W2^T ----------
    for(int task = bid; task < 128; task += nb){
        int b = task >> 5, tl = task & 31;
        int mt = tl >> 3, nt = tl & 7;
        nt128(g_hbuf + (long long)b*SI + (long long)mt*128*Ic,
              g_MW2 + (long long)b*ID + (long long)nt*64*Ic,
              g_obuf + (long long)b*SD + (long long)mt*128*Dc + nt*64,
              Ic, Dc, 0, SH);
    }
    gridSync(nb);

    // ---------- Phase 6: final combine ----------
    for(int task = bid; task < Bc*Sc; task += nb){
        int b = task >> 9;
        long long idx = (long long)task*Dc + tid;
        float qv = g_q[idx];
        float ov = g_obuf[idx];
        float ln = g_Mln[b*Dc + tid];
        float s2 = blockReduce(ov*ov, sred);
        float n = rsqrtf(s2*(1.f/Dc) + 1e-6f);
        out[idx] = qv + ov*n*ln;
    }
}

extern "C" void kernel_launch(void* const* d_in, const int* in_sizes, int n_in,
                              void* d_out, int out_size){
    const float* x   = (const float*)d_in[0];
    const float* wq  = (const float*)d_in[1];
    const float* wk  = (const float*)d_in[2];
    const float* wv  = (const float*)d_in[3];
    const float* qn  = (const float*)d_in[4];
    const float* kn  = (const float*)d_in[5];
    const float* alw = (const float*)d_in[6];
    const float* thw = (const float*)d_in[7];
    const float* etw = (const float*)d_in[8];
    const float* w1  = (const float*)d_in[9];
    const float* w2  = (const float*)d_in[10];
    const float* lnw = (const float*)d_in[11];
    float* out = (float*)d_out;

    int nsm = 0;
    cudaDeviceGetAttribute(&nsm, cudaDevAttrMultiProcessorCount, 0);
    if(nsm <= 0) nsm = 148;

    mega_kernel<<<nsm, 512>>>(x, wq, wk, wv, qn, kn, alw, thw, etw, w1, w2, lnw, out, nsm);
}